// round 2
// baseline (speedup 1.0000x reference)
#include <cuda_runtime.h>
#include <math.h>

#define SEQ 2048
#define DM  2048
#define NH  16
#define DK  128
#define FIB 64

// ---------------- static scratch (no allocations allowed) ----------------
__device__ float g_Q[(size_t)SEQ * DM];
__device__ float g_K[(size_t)SEQ * DM];
__device__ float g_V[(size_t)SEQ * DM];
__device__ float g_O[(size_t)SEQ * DM];
__device__ float g_FP[(size_t)SEQ * FIB];
__device__ float g_G[(size_t)SEQ * FIB];
__device__ float g_MOD[(size_t)SEQ * SEQ];
__device__ float g_S[(size_t)NH * SEQ * SEQ];   // 256 MB attention scores
__device__ float g_mi[FIB];
__device__ float g_metric[FIB * FIB];
__device__ float g_curv[SEQ];

// ---------------- generic tiled SGEMM: C = alpha * A(MxK) * B(NxK)^T -----
// A row-major lda, B row-major ldb (K contiguous for both), C row-major ldc.
// M is always a multiple of 128 in all call sites; N may be smaller than the
// 128-wide tile (guarded). K must be a multiple of 16.
// Optional epilogue: + bias[col] and + coupling*(mod[row*N+col] + curv[col]).
__global__ __launch_bounds__(256) void sgemm_nt(
    const float* __restrict__ A, const float* __restrict__ B, float* __restrict__ C,
    int N, int K, int lda, int ldb, int ldc,
    long long zA, long long zB, long long zC,
    float alpha,
    const float* __restrict__ bias,
    const float* __restrict__ mod, const float* __restrict__ curv, float coupling)
{
    __shared__ float As[16][132];
    __shared__ float Bs[16][132];

    A += (long long)blockIdx.z * zA;
    B += (long long)blockIdx.z * zB;
    C += (long long)blockIdx.z * zC;

    const int bm = blockIdx.y * 128;
    const int bn = blockIdx.x * 128;
    const int tid = threadIdx.x;
    const int lr  = tid >> 2;          // 0..63
    const int lc  = (tid & 3) << 2;    // 0,4,8,12
    const int tm  = tid >> 4;          // 0..15
    const int tn  = tid & 15;          // 0..15

    float acc[8][8];
#pragma unroll
    for (int i = 0; i < 8; i++)
#pragma unroll
        for (int j = 0; j < 8; j++) acc[i][j] = 0.f;

    for (int k0 = 0; k0 < K; k0 += 16) {
#pragma unroll
        for (int h = 0; h < 2; h++) {
            const int r = lr + h * 64;
            float4 a = *(const float4*)(A + (long long)(bm + r) * lda + k0 + lc);
            As[lc + 0][r] = a.x; As[lc + 1][r] = a.y;
            As[lc + 2][r] = a.z; As[lc + 3][r] = a.w;

            float4 b = make_float4(0.f, 0.f, 0.f, 0.f);
            if (bn + r < N)
                b = *(const float4*)(B + (long long)(bn + r) * ldb + k0 + lc);
            Bs[lc + 0][r] = b.x; Bs[lc + 1][r] = b.y;
            Bs[lc + 2][r] = b.z; Bs[lc + 3][r] = b.w;
        }
        __syncthreads();

#pragma unroll
        for (int k = 0; k < 16; k++) {
            float ra[8], rb[8];
#pragma unroll
            for (int i = 0; i < 8; i++) ra[i] = As[k][tm * 8 + i];
#pragma unroll
            for (int j = 0; j < 8; j++) rb[j] = Bs[k][tn * 8 + j];
#pragma unroll
            for (int i = 0; i < 8; i++)
#pragma unroll
                for (int j = 0; j < 8; j++)
                    acc[i][j] = fmaf(ra[i], rb[j], acc[i][j]);
        }
        __syncthreads();
    }

#pragma unroll
    for (int i = 0; i < 8; i++) {
        const int row = bm + tm * 8 + i;
#pragma unroll
        for (int j = 0; j < 8; j++) {
            const int col = bn + tn * 8 + j;
            if (col < N) {
                float v = acc[i][j] * alpha;
                if (bias) v += bias[col];
                if (mod)  v += coupling * (mod[(long long)row * N + col] + curv[col]);
                C[(long long)row * ldc + col] = v;
            }
        }
    }
}

// ---------------- SGEMM NN: C = A(MxK) * B(KxN) -- used for P @ V ---------
// N == 128 exactly at the call site (one n-tile), K multiple of 16.
__global__ __launch_bounds__(256) void sgemm_nn(
    const float* __restrict__ A, const float* __restrict__ B, float* __restrict__ C,
    int K, int lda, int ldb, int ldc,
    long long zA, long long zB, long long zC)
{
    __shared__ float As[16][132];
    __shared__ float Bs[16][132];

    A += (long long)blockIdx.z * zA;
    B += (long long)blockIdx.z * zB;
    C += (long long)blockIdx.z * zC;

    const int bm = blockIdx.y * 128;
    const int bn = blockIdx.x * 128;
    const int tid = threadIdx.x;
    const int lr  = tid >> 2;
    const int lc  = (tid & 3) << 2;
    const int tm  = tid >> 4;
    const int tn  = tid & 15;

    float acc[8][8];
#pragma unroll
    for (int i = 0; i < 8; i++)
#pragma unroll
        for (int j = 0; j < 8; j++) acc[i][j] = 0.f;

    for (int k0 = 0; k0 < K; k0 += 16) {
        // A tile 128x16, transposed into As[k][m]
#pragma unroll
        for (int h = 0; h < 2; h++) {
            const int r = lr + h * 64;
            float4 a = *(const float4*)(A + (long long)(bm + r) * lda + k0 + lc);
            As[lc + 0][r] = a.x; As[lc + 1][r] = a.y;
            As[lc + 2][r] = a.z; As[lc + 3][r] = a.w;
        }
        // B tile 16x128, natural layout Bs[k][n]
#pragma unroll
        for (int it = 0; it < 2; it++) {
            const int idx  = tid + it * 256;       // 0..511
            const int brow = idx >> 5;             // 0..15
            const int bcol = (idx & 31) << 2;      // 0..124
            float4 b = *(const float4*)(B + (long long)(k0 + brow) * ldb + bn + bcol);
            Bs[brow][bcol + 0] = b.x; Bs[brow][bcol + 1] = b.y;
            Bs[brow][bcol + 2] = b.z; Bs[brow][bcol + 3] = b.w;
        }
        __syncthreads();

#pragma unroll
        for (int k = 0; k < 16; k++) {
            float ra[8], rb[8];
#pragma unroll
            for (int i = 0; i < 8; i++) ra[i] = As[k][tm * 8 + i];
#pragma unroll
            for (int j = 0; j < 8; j++) rb[j] = Bs[k][tn * 8 + j];
#pragma unroll
            for (int i = 0; i < 8; i++)
#pragma unroll
                for (int j = 0; j < 8; j++)
                    acc[i][j] = fmaf(ra[i], rb[j], acc[i][j]);
        }
        __syncthreads();
    }

#pragma unroll
    for (int i = 0; i < 8; i++) {
        const int row = bm + tm * 8 + i;
#pragma unroll
        for (int j = 0; j < 8; j++) {
            const int col = bn + tn * 8 + j;
            C[(long long)row * ldc + col] = acc[i][j];
        }
    }
}

// ---------------- mean of FP over the sequence axis -> g_mi --------------
__global__ __launch_bounds__(256) void fp_mean_kernel()
{
    const int f = blockIdx.x;       // 0..63
    const int t = threadIdx.x;
    float s = 0.f;
    for (int i = t; i < SEQ; i += 256) s += g_FP[(size_t)i * FIB + f];
    __shared__ float red[256];
    red[t] = s;
    __syncthreads();
    for (int off = 128; off > 0; off >>= 1) {
        if (t < off) red[t] += red[t + off];
        __syncthreads();
    }
    if (t == 0) g_mi[f] = red[0] * (1.f / (float)SEQ);
}

// ---------------- fiber MLP + metric + analytic ci.mean ------------------
// mi = concat(fp.mean, consciousness)[:, :64] == fp.mean (truncation drops cs).
// ci.mean = mi^T M mi + sum_f mi[f]*diag(curv_mod)[f] / FIB-normalized means
__global__ __launch_bounds__(64) void fiber_mlp_kernel(
    const float* __restrict__ fm1_w, const float* __restrict__ fm1_b,
    const float* __restrict__ fm2_w, const float* __restrict__ fm2_b,
    const float* __restrict__ cmod, float* cimean_out)
{
    __shared__ float mi[FIB], h[FIB / 2], raw[FIB];
    const int t = threadIdx.x;
    mi[t] = g_mi[t];
    __syncthreads();
    if (t < 32) {
        float s = fm1_b[t];
        for (int f = 0; f < FIB; f++) s = fmaf(fm1_w[t * FIB + f], mi[f], s);
        h[t] = fmaxf(s, 0.f);
    }
    __syncthreads();
    float r = fm2_b[t];
    for (int j = 0; j < 32; j++) r = fmaf(fm2_w[t * 32 + j], h[j], r);
    raw[t] = r;
    __syncthreads();
    for (int gc = 0; gc < FIB; gc++)
        g_metric[t * FIB + gc] = raw[t] * raw[gc] + ((t == gc) ? 0.1f : 0.f);
    if (t == 0 && cimean_out) {
        float acc = 0.f;
        for (int f = 0; f < FIB; f++) {
            float s = 0.f;
            for (int gc = 0; gc < FIB; gc++) {
                float m = raw[f] * raw[gc] + ((f == gc) ? 0.1f : 0.f);
                s = fmaf(m, mi[gc], s);
            }
            acc = fmaf(mi[f], s, acc);
            acc = fmaf(mi[f], cmod[f * (FIB + 1)], acc);   // diag term
        }
        *cimean_out = acc;
    }
}

// ---------------- G = FP @ metric  and  curv[i] = FP[i,:].diag -----------
__global__ __launch_bounds__(256) void g_and_curv_kernel(const float* __restrict__ cmod)
{
    __shared__ float Ms[FIB * FIB];
    __shared__ float dg[FIB];
    const int t = threadIdx.x;
    for (int i = t; i < FIB * FIB; i += 256) Ms[i] = g_metric[i];
    if (t < FIB) dg[t] = cmod[t * (FIB + 1)];
    __syncthreads();

    const int idx  = blockIdx.x * 256 + t;   // SEQ*FIB total
    const int i    = idx >> 6;
    const int gcol = idx & 63;
    const float* fr = g_FP + (size_t)i * FIB;
    float s = 0.f;
#pragma unroll 8
    for (int f = 0; f < FIB; f++) s = fmaf(fr[f], Ms[f * FIB + gcol], s);
    g_G[idx] = s;
    if (gcol == 0) {
        float c = 0.f;
#pragma unroll 8
        for (int f = 0; f < FIB; f++) c = fmaf(fr[f], dg[f], c);
        g_curv[i] = c;
    }
}

// ---------------- row softmax over g_S (NH*SEQ rows of len SEQ) ----------
// float4-vectorized: each thread owns 2 float4 = 8 elements of the row.
__global__ __launch_bounds__(256) void softmax_kernel()
{
    float4* p = (float4*)(g_S + (size_t)blockIdx.x * SEQ);
    const int t = threadIdx.x;
    float4 v0 = p[t];
    float4 v1 = p[t + 256];
    float m = fmaxf(fmaxf(fmaxf(v0.x, v0.y), fmaxf(v0.z, v0.w)),
                    fmaxf(fmaxf(v1.x, v1.y), fmaxf(v1.z, v1.w)));
    __shared__ float red[256];
    red[t] = m;
    __syncthreads();
    for (int off = 128; off > 0; off >>= 1) {
        if (t < off) red[t] = fmaxf(red[t], red[t + off]);
        __syncthreads();
    }
    m = red[0];
    __syncthreads();
    v0.x = __expf(v0.x - m); v0.y = __expf(v0.y - m);
    v0.z = __expf(v0.z - m); v0.w = __expf(v0.w - m);
    v1.x = __expf(v1.x - m); v1.y = __expf(v1.y - m);
    v1.z = __expf(v1.z - m); v1.w = __expf(v1.w - m);
    float s = (v0.x + v0.y + v0.z + v0.w) + (v1.x + v1.y + v1.z + v1.w);
    red[t] = s;
    __syncthreads();
    for (int off = 128; off > 0; off >>= 1) {
        if (t < off) red[t] += red[t + off];
        __syncthreads();
    }
    const float inv = 1.f / red[0];
    v0.x *= inv; v0.y *= inv; v0.z *= inv; v0.w *= inv;
    v1.x *= inv; v1.y *= inv; v1.z *= inv; v1.w *= inv;
    p[t] = v0;
    p[t + 256] = v1;
}

// ---------------- launch --------------------------------------------------
extern "C" void kernel_launch(void* const* d_in, const int* in_sizes, int n_in,
                              void* d_out, int out_size)
{
    const float* x       = (const float*)d_in[0];
    // d_in[1] = consciousness_state: truncated away by the reference math
    const float* wq      = (const float*)d_in[2];
    const float* wk      = (const float*)d_in[3];
    const float* wv      = (const float*)d_in[4];
    const float* wo_w    = (const float*)d_in[5];
    const float* wo_b    = (const float*)d_in[6];
    const float* fiber_w = (const float*)d_in[7];
    const float* fiber_b = (const float*)d_in[8];
    const float* fm1_w   = (const float*)d_in[9];
    const float* fm1_b   = (const float*)d_in[10];
    const float* fm2_w   = (const float*)d_in[11];
    const float* fm2_b   = (const float*)d_in[12];
    const float* cmod    = (const float*)d_in[13];
    float* out = (float*)d_out;

    float *Q, *Kp, *V, *O, *FP, *G, *MOD, *S, *CURV;
    cudaGetSymbolAddress((void**)&Q,    g_Q);
    cudaGetSymbolAddress((void**)&Kp,   g_K);
    cudaGetSymbolAddress((void**)&V,    g_V);
    cudaGetSymbolAddress((void**)&O,    g_O);
    cudaGetSymbolAddress((void**)&FP,   g_FP);
    cudaGetSymbolAddress((void**)&G,    g_G);
    cudaGetSymbolAddress((void**)&MOD,  g_MOD);
    cudaGetSymbolAddress((void**)&S,    g_S);
    cudaGetSymbolAddress((void**)&CURV, g_curv);

    float* cimean_out =
        (out_size > SEQ * DM) ? (out + (size_t)SEQ * DM) : (float*)0;

    const dim3 blk(256);
    const dim3 gProj(DM / 128, SEQ / 128, 1);

    // 1-3. Q/K/V = x @ W^T
    sgemm_nt<<<gProj, blk>>>(x, wq, Q,  DM, DM, DM, DM, DM, 0, 0, 0, 1.f, 0, 0, 0, 0.f);
    sgemm_nt<<<gProj, blk>>>(x, wk, Kp, DM, DM, DM, DM, DM, 0, 0, 0, 1.f, 0, 0, 0, 0.f);
    sgemm_nt<<<gProj, blk>>>(x, wv, V,  DM, DM, DM, DM, DM, 0, 0, 0, 1.f, 0, 0, 0, 0.f);

    // 4. FP = x @ fiber_w^T + fiber_b   (N = 64, one partial n-tile)
    sgemm_nt<<<dim3(1, SEQ / 128, 1), blk>>>(x, fiber_w, FP, FIB, DM, DM, DM, FIB,
                                             0, 0, 0, 1.f, fiber_b, 0, 0, 0.f);

    // 5. mi = mean_s FP
    fp_mean_kernel<<<FIB, 256>>>();

    // 6. metric + analytic ci.mean -> tail of d_out
    fiber_mlp_kernel<<<1, FIB>>>(fm1_w, fm1_b, fm2_w, fm2_b, cmod, cimean_out);

    // 7. G = FP @ metric, curv
    g_and_curv_kernel<<<(SEQ * FIB) / 256, 256>>>(cmod);

    // 8. MOD = G @ FP^T  (K = 64)
    sgemm_nt<<<dim3(SEQ / 128, SEQ / 128, 1), blk>>>(G, FP, MOD, SEQ, FIB, FIB, FIB, SEQ,
                                                     0, 0, 0, 1.f, 0, 0, 0, 0.f);

    // 9. scores[h] = Qh @ Kh^T / sqrt(dk) + 0.1*(MOD + curv[col])
    sgemm_nt<<<dim3(SEQ / 128, SEQ / 128, NH), blk>>>(
        Q, Kp, S, SEQ, DK, DM, DM, SEQ,
        (long long)DK, (long long)DK, (long long)SEQ * SEQ,
        1.f / sqrtf((float)DK), 0, MOD, CURV, 0.1f);

    // 10. softmax rows
    softmax_kernel<<<NH * SEQ, 256>>>();

    // 11. O[h] = P[h] @ V[h]   (N = 128 per head)
    sgemm_nn<<<dim3(1, SEQ / 128, NH), blk>>>(
        S, V, O, SEQ, SEQ, DM, DM,
        (long long)SEQ * SEQ, (long long)DK, (long long)DK);

    // 12. out = O @ wo_w^T + wo_b
    sgemm_nt<<<gProj, blk>>>(O, wo_w, out, DM, DM, DM, DM, DM, 0, 0, 0, 1.f, wo_b, 0, 0, 0.f);
}

// round 11
// speedup vs baseline: 3.0761x; 3.0761x over previous
#include <cuda_runtime.h>
#include <math.h>
#include <stdint.h>

#define SEQ 2048
#define DM  2048
#define NH  16
#define DK  128
#define FIB 64

// ---------------- static scratch ----------------
__device__ float g_X [(size_t)SEQ * DM];
__device__ float g_WQ[(size_t)DM * DM];
__device__ float g_WK[(size_t)DM * DM];
__device__ float g_WV[(size_t)DM * DM];
__device__ float g_WO[(size_t)DM * DM];
__device__ float g_FW[(size_t)FIB * DM];
__device__ float g_Q [(size_t)SEQ * DM];
__device__ float g_K [(size_t)SEQ * DM];
__device__ float g_VT[(size_t)DM * SEQ];   // V transposed (DM x SEQ)
__device__ float g_O [(size_t)SEQ * DM];
__device__ float g_FP[(size_t)SEQ * FIB];
__device__ float g_G [(size_t)SEQ * FIB];
__device__ float g_MOD[(size_t)SEQ * SEQ];
__device__ float g_S [(size_t)NH * SEQ * SEQ];
__device__ float g_xbar[DM];
__device__ float g_mi[FIB];
__device__ float g_metric[FIB * FIB];
__device__ float g_curv[SEQ];

// ---------------- helpers ----------------
__device__ __forceinline__ uint32_t smem_u32(const void* p) {
    uint32_t a;
    asm("{ .reg .u64 t; cvta.to.shared.u64 t, %1; cvt.u32.u64 %0, t; }" : "=r"(a) : "l"(p));
    return a;
}
__device__ __forceinline__ float tf32r(float x) {
    uint32_t u;
    asm("cvt.rna.tf32.f32 %0, %1;" : "=r"(u) : "f"(x));
    return __uint_as_float(u);
}
__device__ __forceinline__ void cp16(uint32_t s, const void* g) {
    asm volatile("cp.async.cg.shared.global [%0], [%1], 16;" :: "r"(s), "l"(g));
}
__device__ __forceinline__ void cp_commit() { asm volatile("cp.async.commit_group;" ::: "memory"); }
__device__ __forceinline__ void cp_wait_all() { asm volatile("cp.async.wait_group 0;" ::: "memory"); }

// m16n8k8 tf32 mma: D = A*B + D (A row-major, B col-major)
__device__ __forceinline__ void mma8(float* c, const uint32_t* a, const uint32_t* b) {
    asm volatile(
        "mma.sync.aligned.m16n8k8.row.col.f32.tf32.tf32.f32 "
        "{%0,%1,%2,%3}, {%4,%5,%6,%7}, {%8,%9}, {%0,%1,%2,%3};"
        : "+f"(c[0]), "+f"(c[1]), "+f"(c[2]), "+f"(c[3])
        : "r"(a[0]), "r"(a[1]), "r"(a[2]), "r"(a[3]), "r"(b[0]), "r"(b[1]));
}

#define KT    32
#define ASTR  36                       // padded row stride (floats): conflict-free frags
#define TILEF (128 * ASTR)             // floats per tile buffer

// ---------------- tf32 tensor-core GEMM: C = alpha*A(MxK)·B(NxK)^T + epi ----
__global__ __launch_bounds__(256) void mma_gemm(
    const float* __restrict__ A, const float* __restrict__ B, float* __restrict__ C,
    int N, int K, int lda, int ldb, int ldc,
    long long zA, long long zB, long long zC,
    float alpha, const float* __restrict__ bias,
    const float* __restrict__ mod, int ldmod, const float* __restrict__ curv,
    float coupling, int storeT, int roundC)
{
    extern __shared__ float smf[];
    float* A0 = smf;
    float* B0 = A0 + TILEF;
    float* A1 = B0 + TILEF;
    float* B1 = A1 + TILEF;

    const int tid = threadIdx.x;
    const int wid = tid >> 5, lane = tid & 31;
    const int wm = wid >> 2, wn = wid & 3;     // 2 x 4 warp grid
    const int g = lane >> 2, t = lane & 3;

    A += (long long)blockIdx.z * zA;
    B += (long long)blockIdx.z * zB;
    C += (long long)blockIdx.z * zC;
    const int bm = blockIdx.y * 128;
    const int bn = blockIdx.x * 128;
    const float* Ab = A + (long long)bm * lda;
    const float* Bb = B + (long long)bn * ldb;

    float acc[4][4][4];
#pragma unroll
    for (int mt = 0; mt < 4; mt++)
#pragma unroll
        for (int nt = 0; nt < 4; nt++)
#pragma unroll
            for (int r = 0; r < 4; r++) acc[mt][nt][r] = 0.f;

    const int NKT = K / KT;

    auto load_tiles = [&](float* As, float* Bs, int k0) {
        for (int c = tid; c < 1024; c += 256) {
            const int row = c >> 3;
            const int k4  = (c & 7) << 2;
            cp16(smem_u32(As + row * ASTR + k4), Ab + (long long)row * lda + k0 + k4);
            if (bn + row < N) {
                cp16(smem_u32(Bs + row * ASTR + k4), Bb + (long long)row * ldb + k0 + k4);
            } else {
                *(float4*)(Bs + row * ASTR + k4) = make_float4(0.f, 0.f, 0.f, 0.f);
            }
        }
    };

    load_tiles(A0, B0, 0);
    cp_commit();

    for (int kt = 0; kt < NKT; kt++) {
        float* As = (kt & 1) ? A1 : A0;
        float* Bs = (kt & 1) ? B1 : B0;
        cp_wait_all();
        __syncthreads();
        if (kt + 1 < NKT) {
            load_tiles((kt & 1) ? A0 : A1, (kt & 1) ? B0 : B1, (kt + 1) * KT);
            cp_commit();
        }
#pragma unroll
        for (int ks = 0; ks < 4; ks++) {
            const int k = ks * 8;
            uint32_t af[4][4], bf[4][2];
#pragma unroll
            for (int mt = 0; mt < 4; mt++) {
                const int r = wm * 64 + mt * 16 + g;
                af[mt][0] = __float_as_uint(As[r * ASTR + k + t]);
                af[mt][1] = __float_as_uint(As[(r + 8) * ASTR + k + t]);
                af[mt][2] = __float_as_uint(As[r * ASTR + k + t + 4]);
                af[mt][3] = __float_as_uint(As[(r + 8) * ASTR + k + t + 4]);
            }
#pragma unroll
            for (int nt = 0; nt < 4; nt++) {
                const int cidx = wn * 32 + nt * 8 + g;
                bf[nt][0] = __float_as_uint(Bs[cidx * ASTR + k + t]);
                bf[nt][1] = __float_as_uint(Bs[cidx * ASTR + k + t + 4]);
            }
#pragma unroll
            for (int mt = 0; mt < 4; mt++)
#pragma unroll
                for (int nt = 0; nt < 4; nt++)
                    mma8(acc[mt][nt], af[mt], bf[nt]);
        }
        __syncthreads();
    }

    // ---------------- epilogue ----------------
    if (!storeT) {
#pragma unroll
        for (int mt = 0; mt < 4; mt++) {
#pragma unroll
            for (int nt = 0; nt < 4; nt++) {
                const int row0 = bm + wm * 64 + mt * 16 + g;
                const int col0 = bn + wn * 32 + nt * 8 + 2 * t;
                if (col0 < N) {
#pragma unroll
                    for (int h = 0; h < 2; h++) {
                        const int row = row0 + h * 8;
                        float v0 = acc[mt][nt][h * 2 + 0] * alpha;
                        float v1 = acc[mt][nt][h * 2 + 1] * alpha;
                        if (bias) { v0 += bias[col0]; v1 += bias[col0 + 1]; }
                        if (mod) {
                            const float* mr = mod + (long long)row * ldmod;
                            v0 += coupling * (mr[col0] + curv[col0]);
                            v1 += coupling * (mr[col0 + 1] + curv[col0 + 1]);
                        }
                        if (roundC) { v0 = tf32r(v0); v1 = tf32r(v1); }
                        *(float2*)(C + (long long)row * ldc + col0) = make_float2(v0, v1);
                    }
                }
            }
        }
    } else {
        __syncthreads();
        for (int p = 0; p < 4; p++) {
            if (wn == p) {
#pragma unroll
                for (int mt = 0; mt < 4; mt++) {
#pragma unroll
                    for (int nt = 0; nt < 4; nt++) {
                        const int r0 = wm * 64 + mt * 16 + g;
                        const int cl = nt * 8 + 2 * t;
                        smf[cl * 132 + r0]           = acc[mt][nt][0];
                        smf[(cl + 1) * 132 + r0]     = acc[mt][nt][1];
                        smf[cl * 132 + r0 + 8]       = acc[mt][nt][2];
                        smf[(cl + 1) * 132 + r0 + 8] = acc[mt][nt][3];
                    }
                }
            }
            __syncthreads();
            for (int idx = tid; idx < 32 * 32; idx += 256) {
                const int c  = idx >> 5;
                const int r4 = (idx & 31) << 2;
                float4 v = *(float4*)&smf[c * 132 + r4];
                v.x *= alpha; v.y *= alpha; v.z *= alpha; v.w *= alpha;
                if (roundC) { v.x = tf32r(v.x); v.y = tf32r(v.y); v.z = tf32r(v.z); v.w = tf32r(v.w); }
                *(float4*)(C + (long long)(bn + p * 32 + c) * ldc + bm + r4) = v;
            }
            __syncthreads();
        }
    }
}

// ---------------- elementwise tf32 round (RN) ----------------
__global__ __launch_bounds__(256) void round_tf32_kernel(const float4* __restrict__ in,
                                                         float4* __restrict__ out, int n4)
{
    int i = blockIdx.x * 256 + threadIdx.x;
    if (i < n4) {
        float4 v = in[i];
        v.x = tf32r(v.x); v.y = tf32r(v.y); v.z = tf32r(v.z); v.w = tf32r(v.w);
        out[i] = v;
    }
}

// ---------------- exact fp32 mi path: xbar = mean_s(x), mi = xbar@FW^T+b --
__global__ __launch_bounds__(256) void xbar_kernel(const float* __restrict__ x)
{
    const int d = blockIdx.x * 256 + threadIdx.x;   // DM columns
    float s = 0.f;
    for (int i = 0; i < SEQ; i++) s += x[(size_t)i * DM + d];
    g_xbar[d] = s * (1.f / (float)SEQ);
}

__global__ __launch_bounds__(256) void mi_kernel(const float* __restrict__ fiber_w,
                                                 const float* __restrict__ fiber_b)
{
    const int f = blockIdx.x;       // FIB blocks
    const int t = threadIdx.x;
    const float* wr = fiber_w + (size_t)f * DM;
    float s = 0.f;
    for (int d = t; d < DM; d += 256) s += g_xbar[d] * wr[d];
    __shared__ float red[256];
    red[t] = s;
    __syncthreads();
    for (int off = 128; off > 0; off >>= 1) {
        if (t < off) red[t] += red[t + off];
        __syncthreads();
    }
    if (t == 0) g_mi[f] = red[0] + fiber_b[f];
}

// ---------------- fiber MLP + metric + analytic ci.mean (exact mi) -------
__global__ __launch_bounds__(64) void fiber_mlp_kernel(
    const float* __restrict__ fm1_w, const float* __restrict__ fm1_b,
    const float* __restrict__ fm2_w, const float* __restrict__ fm2_b,
    const float* __restrict__ cmod, float* cimean_out)
{
    __shared__ float mi[FIB], h[FIB / 2], raw[FIB];
    const int t = threadIdx.x;
    mi[t] = g_mi[t];
    __syncthreads();
    if (t < 32) {
        float s = fm1_b[t];
        for (int f = 0; f < FIB; f++) s = fmaf(fm1_w[t * FIB + f], mi[f], s);
        h[t] = fmaxf(s, 0.f);
    }
    __syncthreads();
    float r = fm2_b[t];
    for (int j = 0; j < 32; j++) r = fmaf(fm2_w[t * 32 + j], h[j], r);
    raw[t] = r;
    __syncthreads();
    for (int gc = 0; gc < FIB; gc++)
        g_metric[t * FIB + gc] = raw[t] * raw[gc] + ((t == gc) ? 0.1f : 0.f);
    if (t == 0 && cimean_out) {
        float acc = 0.f;
        for (int f = 0; f < FIB; f++) {
            float s = 0.f;
            for (int gc = 0; gc < FIB; gc++) {
                float m = raw[f] * raw[gc] + ((f == gc) ? 0.1f : 0.f);
                s = fmaf(m, mi[gc], s);
            }
            acc = fmaf(mi[f], s, acc);
            acc = fmaf(mi[f], cmod[f * (FIB + 1)], acc);
        }
        *cimean_out = acc;
    }
}

// G = FP @ metric (tf32-rounded store), curv[i] = FP[i,:].diag(cmod)
__global__ __launch_bounds__(256) void g_and_curv_kernel(const float* __restrict__ cmod)
{
    __shared__ float Ms[FIB * FIB];
    __shared__ float dg[FIB];
    const int t = threadIdx.x;
    for (int i = t; i < FIB * FIB; i += 256) Ms[i] = g_metric[i];
    if (t < FIB) dg[t] = cmod[t * (FIB + 1)];
    __syncthreads();

    const int idx  = blockIdx.x * 256 + t;
    const int i    = idx >> 6;
    const int gcol = idx & 63;
    const float* fr = g_FP + (size_t)i * FIB;
    float s = 0.f;
#pragma unroll 8
    for (int f = 0; f < FIB; f++) s = fmaf(fr[f], Ms[f * FIB + gcol], s);
    g_G[idx] = tf32r(s);
    if (gcol == 0) {
        float c = 0.f;
#pragma unroll 8
        for (int f = 0; f < FIB; f++) c = fmaf(fr[f], dg[f], c);
        g_curv[i] = c;
    }
}

// ---------------- row softmax, tf32-rounded store (P feeds PV MMA) -------
__global__ __launch_bounds__(256) void softmax_kernel()
{
    float4* p = (float4*)(g_S + (size_t)blockIdx.x * SEQ);
    const int t = threadIdx.x;
    float4 v0 = p[t];
    float4 v1 = p[t + 256];
    float m = fmaxf(fmaxf(fmaxf(v0.x, v0.y), fmaxf(v0.z, v0.w)),
                    fmaxf(fmaxf(v1.x, v1.y), fmaxf(v1.z, v1.w)));
    __shared__ float red[256];
    red[t] = m;
    __syncthreads();
    for (int off = 128; off > 0; off >>= 1) {
        if (t < off) red[t] = fmaxf(red[t], red[t + off]);
        __syncthreads();
    }
    m = red[0];
    __syncthreads();
    v0.x = __expf(v0.x - m); v0.y = __expf(v0.y - m);
    v0.z = __expf(v0.z - m); v0.w = __expf(v0.w - m);
    v1.x = __expf(v1.x - m); v1.y = __expf(v1.y - m);
    v1.z = __expf(v1.z - m); v1.w = __expf(v1.w - m);
    float s = (v0.x + v0.y + v0.z + v0.w) + (v1.x + v1.y + v1.z + v1.w);
    red[t] = s;
    __syncthreads();
    for (int off = 128; off > 0; off >>= 1) {
        if (t < off) red[t] += red[t + off];
        __syncthreads();
    }
    const float inv = 1.f / red[0];
    v0.x = tf32r(v0.x * inv); v0.y = tf32r(v0.y * inv);
    v0.z = tf32r(v0.z * inv); v0.w = tf32r(v0.w * inv);
    v1.x = tf32r(v1.x * inv); v1.y = tf32r(v1.y * inv);
    v1.z = tf32r(v1.z * inv); v1.w = tf32r(v1.w * inv);
    p[t] = v0;
    p[t + 256] = v1;
}

// ---------------- launch --------------------------------------------------
extern "C" void kernel_launch(void* const* d_in, const int* in_sizes, int n_in,
                              void* d_out, int out_size)
{
    const float* x       = (const float*)d_in[0];
    const float* wq      = (const float*)d_in[2];
    const float* wk      = (const float*)d_in[3];
    const float* wv      = (const float*)d_in[4];
    const float* wo_w    = (const float*)d_in[5];
    const float* wo_b    = (const float*)d_in[6];
    const float* fiber_w = (const float*)d_in[7];
    const float* fiber_b = (const float*)d_in[8];
    const float* fm1_w   = (const float*)d_in[9];
    const float* fm1_b   = (const float*)d_in[10];
    const float* fm2_w   = (const float*)d_in[11];
    const float* fm2_b   = (const float*)d_in[12];
    const float* cmod    = (const float*)d_in[13];
    float* out = (float*)d_out;

    float *X, *WQ, *WK, *WV, *WO, *FW, *Q, *Kp, *VT, *O, *FP, *G, *MOD, *S, *CURV;
    cudaGetSymbolAddress((void**)&X,   g_X);
    cudaGetSymbolAddress((void**)&WQ,  g_WQ);
    cudaGetSymbolAddress((void**)&WK,  g_WK);
    cudaGetSymbolAddress((void**)&WV,  g_WV);
    cudaGetSymbolAddress((void**)&WO,  g_WO);
    cudaGetSymbolAddress((void**)&FW,  g_FW);
    cudaGetSymbolAddress((void**)&Q,   g_Q);
    cudaGetSymbolAddress((void**)&Kp,  g_K);
    cudaGetSymbolAddress((void**)&VT,  g_VT);
    cudaGetSymbolAddress((void**)&O,   g_O);
    cudaGetSymbolAddress((void**)&FP,  g_FP);
    cudaGetSymbolAddress((void**)&G,   g_G);
    cudaGetSymbolAddress((void**)&MOD, g_MOD);
    cudaGetSymbolAddress((void**)&S,   g_S);
    cudaGetSymbolAddress((void**)&CURV, g_curv);

    float* cimean_out = (out_size > SEQ * DM) ? (out + (size_t)SEQ * DM) : (float*)0;

    const int SMEM = 4 * TILEF * 4;   // 73728 bytes
    cudaFuncSetAttribute(mma_gemm, cudaFuncAttributeMaxDynamicSharedMemorySize, SMEM);

    const dim3 blk(256);

    // 0. exact fp32 mi path (bypasses tf32 cancellation amplification)
    xbar_kernel<<<DM / 256, blk>>>(x);
    mi_kernel<<<FIB, blk>>>(fiber_w, fiber_b);
    fiber_mlp_kernel<<<1, FIB>>>(fm1_w, fm1_b, fm2_w, fm2_b, cmod, cimean_out);

    // 1. RN-round all external MMA operands to the tf32 grid
    const int n4m = (SEQ * DM) / 4;
    round_tf32_kernel<<<(n4m + 255) / 256, blk>>>((const float4*)x,  (float4*)X,  n4m);
    round_tf32_kernel<<<(n4m + 255) / 256, blk>>>((const float4*)wq, (float4*)WQ, n4m);
    round_tf32_kernel<<<(n4m + 255) / 256, blk>>>((const float4*)wk, (float4*)WK, n4m);
    round_tf32_kernel<<<(n4m + 255) / 256, blk>>>((const float4*)wv, (float4*)WV, n4m);
    round_tf32_kernel<<<(n4m + 255) / 256, blk>>>((const float4*)wo_w, (float4*)WO, n4m);
    const int n4f = (FIB * DM) / 4;
    round_tf32_kernel<<<(n4f + 255) / 256, blk>>>((const float4*)fiber_w, (float4*)FW, n4f);

    const dim3 gProj(DM / 128, SEQ / 128, 1);

    // 2. Q = X @ WQ^T (rounded)
    mma_gemm<<<gProj, blk, SMEM>>>(X, WQ, Q, DM, DM, DM, DM, DM, 0, 0, 0,
                                   1.f, 0, 0, 0, 0, 0.f, 0, 1);
    // 3. K = X @ WK^T (rounded)
    mma_gemm<<<gProj, blk, SMEM>>>(X, WK, Kp, DM, DM, DM, DM, DM, 0, 0, 0,
                                   1.f, 0, 0, 0, 0, 0.f, 0, 1);
    // 4. VT = (X @ WV^T)^T (transposed store, rounded)
    mma_gemm<<<gProj, blk, SMEM>>>(X, WV, VT, DM, DM, DM, DM, SEQ, 0, 0, 0,
                                   1.f, 0, 0, 0, 0, 0.f, 1, 1);
    // 5. FP = X @ FW^T + fiber_b (N=64, rounded)
    mma_gemm<<<dim3(1, SEQ / 128, 1), blk, SMEM>>>(X, FW, FP, FIB, DM, DM, DM, FIB,
                                                   0, 0, 0, 1.f, fiber_b, 0, 0, 0, 0.f, 0, 1);
    // 6. G = FP @ metric, curv
    g_and_curv_kernel<<<(SEQ * FIB) / 256, 256>>>(cmod);

    // 7. MOD = G @ FP^T (K=64)
    mma_gemm<<<dim3(SEQ / 128, SEQ / 128, 1), blk, SMEM>>>(
        G, FP, MOD, SEQ, FIB, FIB, FIB, SEQ, 0, 0, 0, 1.f, 0, 0, 0, 0, 0.f, 0, 0);

    // 8. S[h] = Qh @ Kh^T / sqrt(dk) + 0.1*(MOD + curv[col])
    mma_gemm<<<dim3(SEQ / 128, SEQ / 128, NH), blk, SMEM>>>(
        Q, Kp, S, SEQ, DK, DM, DM, SEQ,
        (long long)DK, (long long)DK, (long long)SEQ * SEQ,
        1.f / sqrtf((float)DK), 0, MOD, SEQ, CURV, 0.1f, 0, 0);

    // 9. softmax (P rounded)
    softmax_kernel<<<NH * SEQ, 256>>>();

    // 10. O[h] = P[h] @ VT[h]^T (rounded)
    mma_gemm<<<dim3(1, SEQ / 128, NH), blk, SMEM>>>(
        S, VT, O, DK, SEQ, SEQ, SEQ, DM,
        (long long)SEQ * SEQ, (long long)DK * SEQ, (long long)DK,
        1.f, 0, 0, 0, 0, 0.f, 0, 1);

    // 11. out = O @ WO^T + wo_b
    mma_gemm<<<gProj, blk, SMEM>>>(O, WO, out, DM, DM, DM, DM, DM, 0, 0, 0,
                                   1.f, wo_b, 0, 0, 0, 0.f, 0, 0);
}